// round 16
// baseline (speedup 1.0000x reference)
#include <cuda_runtime.h>
#include <cuda_bf16.h>

// Problem: out[r] = prod_{k=0..2} sigmoid((ub[k]-logit(bins[idx[r][k]]))/(ub[k]-lb[k]+1e-4))
// 1024 bins, 3 cols, 16.78M rows -> LUT + streaming gather-product.
//
// R15: REP=16 single-table LUT (64KB dynamic smem), 512-thread CTAs,
// 3 CTAs/SM (48 warps/SM, 192KB smem/SM), WITH the 2-deep LDG software
// pipeline. Bank = 16*(idx&1) + (lane&15): only lane pairs (l, l+16) can
// collide -> LDS degree <= 2 deterministic. Pipeline gives 6 outstanding
// LDG.128 per warp so the 48 warps stay fed (R14 showed no-pipeline@48w is
// latency-exposed; R11 showed pipeline@48w fits the 42-reg budget).
// Fallback for unequal bounds: 3 tables REP=4 in the same 64KB.
// Lane-major int4 index loads + warp-carry row stitching as before.

#define N_BINS   1024
#define LUT_FLOATS (N_BINS * 16)       // 16384 floats = 64KB

#define BLOCK_THREADS 512
#define WARPS_PER_BLOCK (BLOCK_THREADS / 32)

// ---------------------------------------------------------------------------
// Warp-carry product stitching round. Lane l of round j holds 4 consecutive
// ints whose columns are (mj, mj+1, mj+2, mj) mod 3. The lane holding a row's
// col-2 element completes the row; leading partials of the next row travel to
// lane+1 via shfl_up, and from lane 31 to lane 0 of the next round.
// ---------------------------------------------------------------------------
template <int MUL>
__device__ __forceinline__ float do_round(int4 v, const float* __restrict__ lut,
                                          int o0, int o1, int o2, int mj,
                                          float qprev, float* __restrict__ out,
                                          unsigned g0, int lane)
{
    float w0 = lut[v.x * MUL + o0];
    float w1 = lut[v.y * MUL + o1];
    float w2 = lut[v.z * MUL + o2];
    float w3 = lut[v.w * MUL + o0];

    float m01 = w0 * w1;
    float w23 = w2 * w3;

    float q = (mj == 0) ? w3 : w23;
    float qin = __shfl_up_sync(0xffffffffu, q, 1);
    if (lane == 0) qin = qprev;

    float res;
    if (mj == 0)      res = m01 * w2;      // full row in-lane
    else if (mj == 1) res = qin * m01;     // qin = col0 from previous lane
    else              res = qin * w0;      // qin = col0*col1 from previous lane

    unsigned rA = g0 / 3u;
    __stcs(&out[rA], res);
    if (mj == 2) __stcs(&out[rA + 1], w1 * w23);  // full row also in-lane

    return __shfl_sync(0xffffffffu, q, 31);
}

template <int MUL>
__device__ __forceinline__ void main_loop(const int4* __restrict__ idx4,
                                          const float* __restrict__ lut,
                                          float* __restrict__ out,
                                          int nchunks, int warpGlobal,
                                          int warpsTotal, int lane,
                                          int offA, int offB, int offC,
                                          int m0, int m1, int m2)
{
    int c = warpGlobal;
    if (c >= nchunks) return;

    // 2-deep software pipeline on the index loads.
    int4 v0 = __ldcs(idx4 + c * 96 + lane);
    int4 v1 = __ldcs(idx4 + c * 96 + 32 + lane);
    int4 v2 = __ldcs(idx4 + c * 96 + 64 + lane);

    while (true) {
        int cn = c + warpsTotal;
        bool more = cn < nchunks;
        int4 n0, n1, n2;
        if (more) {
            n0 = __ldcs(idx4 + cn * 96 + lane);
            n1 = __ldcs(idx4 + cn * 96 + 32 + lane);
            n2 = __ldcs(idx4 + cn * 96 + 64 + lane);
        }

        unsigned Gw = (unsigned)c * 384u + 4u * (unsigned)lane;
        float qprev = 0.0f;
        qprev = do_round<MUL>(v0, lut, offA, offB, offC, m0, qprev, out, Gw,        lane);
        qprev = do_round<MUL>(v1, lut, offC, offA, offB, m1, qprev, out, Gw + 128u, lane);
        (void)  do_round<MUL>(v2, lut, offB, offC, offA, m2, qprev, out, Gw + 256u, lane);

        if (!more) break;
        c = cn; v0 = n0; v1 = n1; v2 = n2;
    }
}

__device__ __forceinline__ float lut_value(float c, float u, float l) {
    float logit = logf(c / (1.0f - c));
    float x = (u - logit) / (u - l + 1e-4f);
    return 1.0f / (1.0f + expf(-x));
}

__global__ void __launch_bounds__(BLOCK_THREADS, 3)
fused_kernel(const float* __restrict__ bin_centers,
             const int4* __restrict__ idx4,
             const float* __restrict__ lb,
             const float* __restrict__ ub,
             float* __restrict__ out, int nchunks)
{
    extern __shared__ float lut[];   // 64KB dynamic

    const float l0 = lb[0], l1 = lb[1], l2 = lb[2];
    const float u0 = ub[0], u1 = ub[1], u2 = ub[2];
    const bool eq = (l0 == l1) && (l1 == l2) && (u0 == u1) && (u1 == u2);

    if (eq) {
        // Single table, REP=16: entry i occupies lut[16i .. 16i+15].
        for (int i = threadIdx.x; i < N_BINS; i += BLOCK_THREADS) {
            float v = lut_value(bin_centers[i], u0, l0);
            float4 v4 = make_float4(v, v, v, v);
            float4* dst = (float4*)&lut[i * 16];
#pragma unroll
            for (int r = 0; r < 4; r++) dst[r] = v4;
        }
    } else {
        // Three tables, REP=4: table k at float offset k*4096 (48KB used).
        for (int i = threadIdx.x; i < 3 * N_BINS; i += BLOCK_THREADS) {
            int bin = i & (N_BINS - 1);
            int col = i >> 10;
            float u = (col == 0) ? u0 : (col == 1) ? u1 : u2;
            float l = (col == 0) ? l0 : (col == 1) ? l1 : l2;
            float v = lut_value(bin_centers[bin], u, l);
            *(float4*)&lut[(size_t)col * 4096 + bin * 4] = make_float4(v, v, v, v);
        }
    }
    __syncthreads();

    const int lane = threadIdx.x & 31;
    const int warpsTotal = gridDim.x * WARPS_PER_BLOCK;
    const int warpGlobal = blockIdx.x * WARPS_PER_BLOCK + (threadIdx.x >> 5);

    // Per-lane column rotation: lane's first element has column m = lane%3.
    const int m  = lane % 3;
    const int m0 = m;
    const int m1 = (m + 2) % 3;
    const int m2 = (m + 1) % 3;

    if (eq) {
        int slot = lane & 15;
        main_loop<16>(idx4, lut, out, nchunks, warpGlobal, warpsTotal, lane,
                      slot, slot, slot, m0, m1, m2);
    } else {
        int slot = lane & 3;
        int t0 = slot, t1 = 4096 + slot, t2 = 8192 + slot;
        int offA = (m == 0) ? t0 : (m == 1) ? t1 : t2;
        int offB = (m == 0) ? t1 : (m == 1) ? t2 : t0;
        int offC = (m == 0) ? t2 : (m == 1) ? t0 : t1;
        main_loop<4>(idx4, lut, out, nchunks, warpGlobal, warpsTotal, lane,
                     offA, offB, offC, m0, m1, m2);
    }
}

// ---------------------------------------------------------------------------
// Tail: per-row direct-compute path for rows not covered by full chunks
// (not hit for 16.78M rows; defensive only).
// ---------------------------------------------------------------------------
__global__ void tail_kernel(const float* __restrict__ bin_centers,
                            const int* __restrict__ idx,
                            const float* __restrict__ lb,
                            const float* __restrict__ ub,
                            float* __restrict__ out,
                            int start_row, int n_rows)
{
    int r = start_row + blockIdx.x * blockDim.x + threadIdx.x;
    if (r >= n_rows) return;
    float p = 1.0f;
#pragma unroll
    for (int k = 0; k < 3; k++) {
        float cb = bin_centers[idx[3 * r + k]];
        float logit = logf(cb / (1.0f - cb));
        float x = (ub[k] - logit) / (ub[k] - lb[k] + 1e-4f);
        p *= 1.0f / (1.0f + expf(-x));
    }
    out[r] = p;
}

extern "C" void kernel_launch(void* const* d_in, const int* in_sizes, int n_in,
                              void* d_out, int out_size)
{
    const float* bin_centers = (const float*)d_in[0];
    const int*   idx         = (const int*)d_in[1];
    const float* lb          = (const float*)d_in[2];
    const float* ub          = (const float*)d_in[3];
    float*       out         = (float*)d_out;

    int n_rows = in_sizes[1] / 3;
    int nchunks = n_rows / 128;   // 128 rows per warp-chunk

    if (nchunks > 0) {
        const int smem = LUT_FLOATS * sizeof(float);   // 64KB
        cudaFuncSetAttribute(fused_kernel,
                             cudaFuncAttributeMaxDynamicSharedMemorySize, smem);
        int blocks = 456;         // 3 CTAs/SM x 152 SMs = one wave, 48 warps/SM
        if (blocks * WARPS_PER_BLOCK > nchunks)
            blocks = (nchunks + WARPS_PER_BLOCK - 1) / WARPS_PER_BLOCK;
        fused_kernel<<<blocks, BLOCK_THREADS, smem>>>(
            bin_centers, (const int4*)idx, lb, ub, out, nchunks);
    }

    int done = nchunks * 128;
    if (done < n_rows) {
        int rem = n_rows - done;
        tail_kernel<<<(rem + 255) / 256, 256>>>(
            bin_centers, idx, lb, ub, out, done, n_rows);
    }
}

// round 17
// speedup vs baseline: 1.0787x; 1.0787x over previous
#include <cuda_runtime.h>
#include <cuda_bf16.h>

// Problem: out[r] = prod_{k=0..2} sigmoid((ub[k]-logit(bins[idx[r][k]]))/(ub[k]-lb[k]+1e-4))
// 1024 bins, 3 cols, 16.78M rows -> LUT + streaming gather-product.
//
// R16: REP=16 single-table LUT (64KB dynamic smem), 1024-thread CTAs,
// 2 CTAs/SM (64 warps/SM, 128KB smem/SM), NO software pipeline (reg cap 32;
// 64 warps x 3 front-batched LDG.128 = 24KB in flight covers DRAM latency,
// proven by R12). Bank = 16*(idx&1) + (lane&15): LDS degree <= 2.
// PLAIN output stores (no __stcs): evict-first on scattered 4B stores was
// correlated with +1.5-3us across R11-R15 (suspected L2 sector write
// amplification); plain STG lets L2 aggregate neighbors.
// Fallback for unequal bounds: 3 tables REP=4 (48KB) in the same alloc.
// Lane-major int4 index loads (__ldcs) + warp-carry row stitching.

#define N_BINS   1024
#define LUT_FLOATS (N_BINS * 16)       // 16384 floats = 64KB

#define BLOCK_THREADS 1024
#define WARPS_PER_BLOCK (BLOCK_THREADS / 32)

// ---------------------------------------------------------------------------
// Warp-carry product stitching round. Lane l of round j holds 4 consecutive
// ints whose columns are (mj, mj+1, mj+2, mj) mod 3. The lane holding a row's
// col-2 element completes the row; leading partials of the next row travel to
// lane+1 via shfl_up, and from lane 31 to lane 0 of the next round.
// ---------------------------------------------------------------------------
template <int MUL>
__device__ __forceinline__ float do_round(int4 v, const float* __restrict__ lut,
                                          int o0, int o1, int o2, int mj,
                                          float qprev, float* __restrict__ out,
                                          unsigned g0, int lane)
{
    float w0 = lut[v.x * MUL + o0];
    float w1 = lut[v.y * MUL + o1];
    float w2 = lut[v.z * MUL + o2];
    float w3 = lut[v.w * MUL + o0];

    float m01 = w0 * w1;
    float w23 = w2 * w3;

    float q = (mj == 0) ? w3 : w23;
    float qin = __shfl_up_sync(0xffffffffu, q, 1);
    if (lane == 0) qin = qprev;

    float res;
    if (mj == 0)      res = m01 * w2;      // full row in-lane
    else if (mj == 1) res = qin * m01;     // qin = col0 from previous lane
    else              res = qin * w0;      // qin = col0*col1 from previous lane

    unsigned rA = g0 / 3u;
    out[rA] = res;                          // plain STG (no .cs)
    if (mj == 2) out[rA + 1] = w1 * w23;    // full row also in-lane

    return __shfl_sync(0xffffffffu, q, 31);
}

template <int MUL>
__device__ __forceinline__ void main_loop(const int4* __restrict__ idx4,
                                          const float* __restrict__ lut,
                                          float* __restrict__ out,
                                          int nchunks, int warpGlobal,
                                          int warpsTotal, int lane,
                                          int offA, int offB, int offC,
                                          int m0, int m1, int m2)
{
    for (int c = warpGlobal; c < nchunks; c += warpsTotal) {
        int4 v0 = __ldcs(idx4 + c * 96 + lane);
        int4 v1 = __ldcs(idx4 + c * 96 + 32 + lane);
        int4 v2 = __ldcs(idx4 + c * 96 + 64 + lane);

        unsigned Gw = (unsigned)c * 384u + 4u * (unsigned)lane;
        float qprev = 0.0f;
        qprev = do_round<MUL>(v0, lut, offA, offB, offC, m0, qprev, out, Gw,        lane);
        qprev = do_round<MUL>(v1, lut, offC, offA, offB, m1, qprev, out, Gw + 128u, lane);
        (void)  do_round<MUL>(v2, lut, offB, offC, offA, m2, qprev, out, Gw + 256u, lane);
    }
}

__device__ __forceinline__ float lut_value(float c, float u, float l) {
    float logit = logf(c / (1.0f - c));
    float x = (u - logit) / (u - l + 1e-4f);
    return 1.0f / (1.0f + expf(-x));
}

__global__ void __launch_bounds__(BLOCK_THREADS, 2)
fused_kernel(const float* __restrict__ bin_centers,
             const int4* __restrict__ idx4,
             const float* __restrict__ lb,
             const float* __restrict__ ub,
             float* __restrict__ out, int nchunks)
{
    extern __shared__ float lut[];   // 64KB dynamic

    const float l0 = lb[0], l1 = lb[1], l2 = lb[2];
    const float u0 = ub[0], u1 = ub[1], u2 = ub[2];
    const bool eq = (l0 == l1) && (l1 == l2) && (u0 == u1) && (u1 == u2);

    if (eq) {
        // Single table, REP=16: entry i occupies lut[16i .. 16i+15].
        for (int i = threadIdx.x; i < N_BINS; i += BLOCK_THREADS) {
            float v = lut_value(bin_centers[i], u0, l0);
            float4 v4 = make_float4(v, v, v, v);
            float4* dst = (float4*)&lut[i * 16];
#pragma unroll
            for (int r = 0; r < 4; r++) dst[r] = v4;
        }
    } else {
        // Three tables, REP=4: table k at float offset k*4096 (48KB used).
        for (int i = threadIdx.x; i < 3 * N_BINS; i += BLOCK_THREADS) {
            int bin = i & (N_BINS - 1);
            int col = i >> 10;
            float u = (col == 0) ? u0 : (col == 1) ? u1 : u2;
            float l = (col == 0) ? l0 : (col == 1) ? l1 : l2;
            float v = lut_value(bin_centers[bin], u, l);
            *(float4*)&lut[(size_t)col * 4096 + bin * 4] = make_float4(v, v, v, v);
        }
    }
    __syncthreads();

    const int lane = threadIdx.x & 31;
    const int warpsTotal = gridDim.x * WARPS_PER_BLOCK;
    const int warpGlobal = blockIdx.x * WARPS_PER_BLOCK + (threadIdx.x >> 5);

    // Per-lane column rotation: lane's first element has column m = lane%3.
    const int m  = lane % 3;
    const int m0 = m;
    const int m1 = (m + 2) % 3;
    const int m2 = (m + 1) % 3;

    if (eq) {
        int slot = lane & 15;
        main_loop<16>(idx4, lut, out, nchunks, warpGlobal, warpsTotal, lane,
                      slot, slot, slot, m0, m1, m2);
    } else {
        int slot = lane & 3;
        int t0 = slot, t1 = 4096 + slot, t2 = 8192 + slot;
        int offA = (m == 0) ? t0 : (m == 1) ? t1 : t2;
        int offB = (m == 0) ? t1 : (m == 1) ? t2 : t0;
        int offC = (m == 0) ? t2 : (m == 1) ? t0 : t1;
        main_loop<4>(idx4, lut, out, nchunks, warpGlobal, warpsTotal, lane,
                     offA, offB, offC, m0, m1, m2);
    }
}

// ---------------------------------------------------------------------------
// Tail: per-row direct-compute path for rows not covered by full chunks
// (not hit for 16.78M rows; defensive only).
// ---------------------------------------------------------------------------
__global__ void tail_kernel(const float* __restrict__ bin_centers,
                            const int* __restrict__ idx,
                            const float* __restrict__ lb,
                            const float* __restrict__ ub,
                            float* __restrict__ out,
                            int start_row, int n_rows)
{
    int r = start_row + blockIdx.x * blockDim.x + threadIdx.x;
    if (r >= n_rows) return;
    float p = 1.0f;
#pragma unroll
    for (int k = 0; k < 3; k++) {
        float cb = bin_centers[idx[3 * r + k]];
        float logit = logf(cb / (1.0f - cb));
        float x = (ub[k] - logit) / (ub[k] - lb[k] + 1e-4f);
        p *= 1.0f / (1.0f + expf(-x));
    }
    out[r] = p;
}

extern "C" void kernel_launch(void* const* d_in, const int* in_sizes, int n_in,
                              void* d_out, int out_size)
{
    const float* bin_centers = (const float*)d_in[0];
    const int*   idx         = (const int*)d_in[1];
    const float* lb          = (const float*)d_in[2];
    const float* ub          = (const float*)d_in[3];
    float*       out         = (float*)d_out;

    int n_rows = in_sizes[1] / 3;
    int nchunks = n_rows / 128;   // 128 rows per warp-chunk

    if (nchunks > 0) {
        const int smem = LUT_FLOATS * sizeof(float);   // 64KB
        cudaFuncSetAttribute(fused_kernel,
                             cudaFuncAttributeMaxDynamicSharedMemorySize, smem);
        int blocks = 304;         // 2 CTAs/SM x 152 SMs = one wave, 64 warps/SM
        if (blocks * WARPS_PER_BLOCK > nchunks)
            blocks = (nchunks + WARPS_PER_BLOCK - 1) / WARPS_PER_BLOCK;
        fused_kernel<<<blocks, BLOCK_THREADS, smem>>>(
            bin_centers, (const int4*)idx, lb, ub, out, nchunks);
    }

    int done = nchunks * 128;
    if (done < n_rows) {
        int rem = n_rows - done;
        tail_kernel<<<(rem + 255) / 256, 256>>>(
            bin_centers, idx, lb, ub, out, done, n_rows);
    }
}